// round 15
// baseline (speedup 1.0000x reference)
#include <cuda_runtime.h>
#include <cuda_fp16.h>
#include <cstdint>

// Problem constants
#define BT    4096      // B*T
#define CD    1024      // C
#define C3    3072      // 3C
#define TLEN  2048
#define NH    16
#define DH    64

// ---------------------------------------------------------------------------
// Device-global scratch (allocation-free rule) — all plain fp16
// ---------------------------------------------------------------------------
__device__ __half g_xh[BT * CD];       // x fp16
__device__ __half g_wah[CD * C3];      // W_attn fp16
__device__ __half g_wph[CD * CD];      // W_proj fp16
__device__ __half g_qkvh[BT * C3];     // qkv fp16
__device__ __half g_yh[BT * CD];       // attn out fp16

// ---------------------------------------------------------------------------
// helpers
// ---------------------------------------------------------------------------
__device__ __forceinline__ uint32_t smem_u32(const void* p) {
    uint32_t a;
    asm("{ .reg .u64 t; cvta.to.shared.u64 t, %1; cvt.u32.u64 %0, t; }"
        : "=r"(a) : "l"(p));
    return a;
}

#define LDSM_X4(r0, r1, r2, r3, addr)                                          \
    asm volatile("ldmatrix.sync.aligned.m8n8.x4.shared.b16 {%0,%1,%2,%3}, [%4];" \
                 : "=r"(r0), "=r"(r1), "=r"(r2), "=r"(r3) : "r"(addr))

#define LDSM_X4_T(r0, r1, r2, r3, addr)                                        \
    asm volatile("ldmatrix.sync.aligned.m8n8.x4.trans.shared.b16 {%0,%1,%2,%3}, [%4];" \
                 : "=r"(r0), "=r"(r1), "=r"(r2), "=r"(r3) : "r"(addr))

__device__ __forceinline__ void mma_f16(float* d, const uint32_t* a,
                                        const uint32_t* b) {
    asm volatile(
        "mma.sync.aligned.m16n8k16.row.col.f32.f16.f16.f32 "
        "{%0,%1,%2,%3}, {%4,%5,%6,%7}, {%8,%9}, {%0,%1,%2,%3};"
        : "+f"(d[0]), "+f"(d[1]), "+f"(d[2]), "+f"(d[3])
        : "r"(a[0]), "r"(a[1]), "r"(a[2]), "r"(a[3]), "r"(b[0]), "r"(b[1]));
}

__device__ __forceinline__ void cp16(uint32_t s, const void* g) {
    asm volatile("cp.async.cg.shared.global [%0], [%1], 16;" :: "r"(s), "l"(g));
}
#define CP_COMMIT() asm volatile("cp.async.commit_group;" ::: "memory")
#define CP_WAIT0()  asm volatile("cp.async.wait_group 0;" ::: "memory")

// ---------------------------------------------------------------------------
// Merged pre-pass: convert x, W_attn, W_proj fp32 -> fp16 in one launch
// ---------------------------------------------------------------------------
#define XN4  (BT * CD / 4)        // 1048576
#define WAN4 (CD * C3 / 4)        // 786432
#define WPN4 (CD * CD / 4)        // 262144
#define ALLN4 (XN4 + WAN4 + WPN4) // 2097152

__global__ void conv_all(const float* __restrict__ x,
                         const float* __restrict__ wa,
                         const float* __restrict__ wp,
                         __half* __restrict__ xh,
                         __half* __restrict__ wah,
                         __half* __restrict__ wph)
{
    int i = blockIdx.x * blockDim.x + threadIdx.x;
    if (i >= ALLN4) return;
    const float* s; __half* d; int off;
    if (i < XN4)             { s = x;  d = xh;  off = i; }
    else if (i < XN4 + WAN4) { s = wa; d = wah; off = i - XN4; }
    else                     { s = wp; d = wph; off = i - XN4 - WAN4; }
    float4 v = ((const float4*)s)[off];
    __half2 a = __floats2half2_rn(v.x, v.y);
    __half2 b = __floats2half2_rn(v.z, v.w);
    *(uint2*)(d + (size_t)off * 4) = make_uint2(*(uint32_t*)&a, *(uint32_t*)&b);
}

// ---------------------------------------------------------------------------
// Plain fp16 HMMA GEMM: BK=64, 2-stage cp.async, ONE sync per stage.
// C[M,N] = A[M,K] @ B[K,N] + bias    (fp32 accumulate)
// CTA tile 128x128, 8 warps (4m x 2n), warp tile 32x64, 2 CTAs/SM.
// ---------------------------------------------------------------------------
#define GA_ST 72                      // A smem halves/row (64 + 8 pad)
#define GB_ST 136                     // B smem halves/row (128 + 8 pad)
#define SA_SZ (128 * GA_ST)           // 9216 halves
#define SB_SZ (64 * GB_ST)            // 8704 halves
#define STG_H (SA_SZ + SB_SZ)         // 17920 halves per stage
#define GEMM_SMEM_B (2 * STG_H * 2)   // 71680 bytes

template <bool FP16_OUT>
__global__ __launch_bounds__(256, 2) void gemm_f16(
    const __half* __restrict__ Ah_,
    const __half* __restrict__ Bh_,
    const float* __restrict__ bias, float* __restrict__ C,
    __half* __restrict__ Ch,
    int N, int K)
{
    extern __shared__ __half smg[];
    const uint32_t sb = smem_u32(smg);

    const int tid  = threadIdx.x;
    const int wid  = tid >> 5;
    const int lane = tid & 31;
    const int bm   = blockIdx.y * 128;
    const int bn   = blockIdx.x * 128;
    const int wm   = (wid & 3) * 32;
    const int wn   = (wid >> 2) * 64;

    const int nstages = K >> 6;

    auto load_stage = [&](int s) {
        const int k0 = s << 6;
        const uint32_t base = (uint32_t)(s & 1) * STG_H;
        // A: 128 rows x 64k = 1024 cp16
        #pragma unroll
        for (int i = 0; i < 4; i++) {
            int idx = tid + i * 256;
            int r = idx >> 3, c = idx & 7;
            size_t g = (size_t)(bm + r) * K + k0 + c * 8;
            cp16(sb + (base + r * GA_ST + c * 8) * 2, Ah_ + g);
        }
        // B: 64 rows x 128n = 1024 cp16
        #pragma unroll
        for (int i = 0; i < 4; i++) {
            int idx = tid + i * 256;
            int r = idx >> 4, c = idx & 15;
            size_t g = (size_t)(k0 + r) * N + bn + c * 8;
            cp16(sb + (base + SA_SZ + r * GB_ST + c * 8) * 2, Bh_ + g);
        }
        CP_COMMIT();
    };

    float acc[2][8][4];
    #pragma unroll
    for (int i = 0; i < 2; i++)
        #pragma unroll
        for (int j = 0; j < 8; j++)
            #pragma unroll
            for (int r = 0; r < 4; r++) acc[i][j][r] = 0.f;

    const int a_row = wm + (lane & 15);
    const int a_col = (lane >> 4) * 8;
    const int b_row = (lane & 7) + ((lane >> 3) & 1) * 8;
    const int b_col = wn + (lane >> 4) * 8;

    load_stage(0);

    for (int s = 0; s < nstages; s++) {
        // one barrier: publishes waited data AND proves stage s-1 compute done
        CP_WAIT0();
        __syncthreads();
        if (s + 1 < nstages) load_stage(s + 1);

        const uint32_t base = (uint32_t)(s & 1) * STG_H;
        const uint32_t aH_b = sb + base * 2;
        const uint32_t bH_b = aH_b + SA_SZ * 2;

        #pragma unroll
        for (int kk = 0; kk < 64; kk += 16) {
            uint32_t aH[2][4];
            #pragma unroll
            for (int mf = 0; mf < 2; mf++) {
                uint32_t off = ((a_row + mf * 16) * GA_ST + a_col + kk) * 2;
                LDSM_X4(aH[mf][0], aH[mf][1], aH[mf][2], aH[mf][3], aH_b + off);
            }
            #pragma unroll
            for (int nf2 = 0; nf2 < 4; nf2++) {
                uint32_t off = ((b_row + kk) * GB_ST + b_col + nf2 * 16) * 2;
                uint32_t bH[4];
                LDSM_X4_T(bH[0], bH[1], bH[2], bH[3], bH_b + off);
                #pragma unroll
                for (int mf = 0; mf < 2; mf++) {
                    #pragma unroll
                    for (int h = 0; h < 2; h++) {
                        mma_f16(acc[mf][nf2 * 2 + h], aH[mf], &bH[h * 2]);
                    }
                }
            }
        }
    }

    // ---- epilogue ----
    const int rbase = bm + wm + (lane >> 2);
    const int cbase = bn + wn + (lane & 3) * 2;
    #pragma unroll
    for (int mf = 0; mf < 2; mf++) {
        #pragma unroll
        for (int nf = 0; nf < 8; nf++) {
            int col = cbase + nf * 8;
            float b0 = bias[col], b1 = bias[col + 1];
            int r0 = rbase + mf * 16;
            float v00 = acc[mf][nf][0] + b0, v01 = acc[mf][nf][1] + b1;
            float v10 = acc[mf][nf][2] + b0, v11 = acc[mf][nf][3] + b1;
            if (FP16_OUT) {
                __half2 o0 = __floats2half2_rn(v00, v01);
                __half2 o1 = __floats2half2_rn(v10, v11);
                *(uint32_t*)(Ch + (size_t)r0 * N + col)       = *(uint32_t*)&o0;
                *(uint32_t*)(Ch + (size_t)(r0 + 8) * N + col) = *(uint32_t*)&o1;
            } else {
                *(float2*)(C + (size_t)r0 * N + col)       = make_float2(v00, v01);
                *(float2*)(C + (size_t)(r0 + 8) * N + col) = make_float2(v10, v11);
            }
        }
    }
}

// ---------------------------------------------------------------------------
// Causal flash attention, fp16 operands / fp32 acc.
// Q tile 128 rows (8 warps x 16 q-rows, 256 thr); 128-key K/V tiles,
// cp.async double-buffered with ONE sync per tile.
// Grid (16 qtiles, 16 heads, 2 batch). smem 92160 B -> 2 CTAs/SM.
// ---------------------------------------------------------------------------
#define AT_ST 72
#define QT_SZ (128 * AT_ST)                      // 9216 halves
#define KT_SZ (128 * AT_ST)                      // 9216 halves (K or V tile)
#define KV_STG (2 * KT_SZ)                       // 18432 halves per stage
#define ATTN_SMEM_B ((QT_SZ + 2 * KV_STG) * 2)   // 92160 bytes
#define C2 0.18033688011112042f                  // 0.125 * log2(e)

__global__ __launch_bounds__(256, 2) void attn_mma(
    const __half* __restrict__ qh_g, __half* __restrict__ yh)
{
    extern __shared__ __half sma[];
    const uint32_t sb = smem_u32(sma);
    const uint32_t Qh_b = sb;

    const int qt   = (int)gridDim.x - 1 - (int)blockIdx.x;  // heavy first
    const int h    = blockIdx.y;
    const int b    = blockIdx.z;
    const int tid  = threadIdx.x;
    const int wid  = tid >> 5;          // 0..7
    const int lane = tid & 31;
    const int q0   = qt * 128;
    const int wq   = wid * 16;

    // ---- Q tile (128 rows), folded into first cp.async group ----
    {
        const size_t qbase = (size_t)(b * TLEN + q0) * C3 + h * DH;
        #pragma unroll
        for (int i = 0; i < 4; i++) {
            int idx = tid + i * 256;
            int r = idx >> 3, c = idx & 7;
            cp16(Qh_b + (r * AT_ST + c * 8) * 2, qh_g + qbase + (size_t)r * C3 + c * 8);
        }
    }

    auto load_kv = [&](int kt) {
        const uint32_t kvb = sb + (QT_SZ + (uint32_t)(kt & 1) * KV_STG) * 2;
        const size_t kbase = (size_t)(b * TLEN + kt * 128) * C3 + CD + h * DH;
        const size_t vbase = kbase + CD;
        #pragma unroll
        for (int i = 0; i < 4; i++) {
            int idx = tid + i * 256;
            int r = idx >> 3, c = idx & 7;
            uint32_t so = (r * AT_ST + c * 8) * 2;
            cp16(kvb + so,             qh_g + kbase + (size_t)r * C3 + c * 8);
            cp16(kvb + so + KT_SZ * 2, qh_g + vbase + (size_t)r * C3 + c * 8);
        }
        CP_COMMIT();
    };

    load_kv(0);

    float m_i[2] = {-1e30f, -1e30f}, l_i[2] = {0.f, 0.f};
    float ofrag[8][4];
    #pragma unroll
    for (int nt = 0; nt < 8; nt++)
        #pragma unroll
        for (int r = 0; r < 4; r++) ofrag[nt][r] = 0.f;

    const int qa_row = wq + (lane & 15);
    const int qa_col = (lane >> 4) * 8;
    const int kb_row = ((lane >> 4) << 3) + (lane & 7);
    const int kb_col = ((lane >> 3) & 1) * 8;
    const int vb_row = (lane & 7) + ((lane >> 3) & 1) * 8;
    const int vb_col = (lane >> 4) * 8;

    const int nkt = qt + 1;

    for (int kt = 0; kt < nkt; kt++) {
        // one barrier per tile: data visibility + prev-compute completion
        CP_WAIT0();
        __syncthreads();
        if (kt + 1 < nkt) load_kv(kt + 1);

        const uint32_t kvb  = sb + (QT_SZ + (uint32_t)(kt & 1) * KV_STG) * 2;
        const uint32_t Kh_b = kvb;
        const uint32_t Vh_b = kvb + KT_SZ * 2;

        // rel >= 0: this warp has at least one unmasked key in this 128-key tile
        const int rel = q0 + wq + 15 - 128 * kt;
        if (rel >= 0) {
            const int npmax = min(7, rel >> 4);   // 16-key subtiles with work

            // ---- S = Q K^T (raw, unscaled) ----
            float sfrag[16][4];
            #pragma unroll
            for (int nt = 0; nt < 16; nt++)
                #pragma unroll
                for (int r = 0; r < 4; r++) sfrag[nt][r] = 0.f;

            #pragma unroll
            for (int ks = 0; ks < 4; ks++) {
                uint32_t qh[4];
                uint32_t qa = (qa_row * AT_ST + ks * 16 + qa_col) * 2;
                LDSM_X4(qh[0], qh[1], qh[2], qh[3], Qh_b + qa);
                for (int np = 0; np <= npmax; np++) {
                    uint32_t ka = ((np * 16 + kb_row) * AT_ST + ks * 16 + kb_col) * 2;
                    uint32_t kh[4];
                    LDSM_X4(kh[0], kh[1], kh[2], kh[3], Kh_b + ka);
                    mma_f16(sfrag[2*np],   qh, &kh[0]);
                    mma_f16(sfrag[2*np+1], qh, &kh[2]);
                }
            }

            // ---- causal mask (raw domain; covers uncomputed subtiles too) ----
            if (rel < 142) {
                #pragma unroll
                for (int nt = 0; nt < 16; nt++) {
                    #pragma unroll
                    for (int r = 0; r < 4; r++) {
                        int gcol = 128 * kt + nt * 8 + (lane & 3) * 2 + (r & 1);
                        int grow = q0 + wq + (lane >> 2) + (r >> 1) * 8;
                        if (gcol > grow) sfrag[nt][r] = -1e30f;
                    }
                }
            }

            // ---- online softmax: raw max, scale folded into exp2 ----
            float corrv[2], nm[2];
            #pragma unroll
            for (int r = 0; r < 2; r++) {
                float mx = -1e30f;
                #pragma unroll
                for (int nt = 0; nt < 16; nt++)
                    mx = fmaxf(mx, fmaxf(sfrag[nt][2*r], sfrag[nt][2*r+1]));
                mx = fmaxf(mx, __shfl_xor_sync(0xffffffffu, mx, 1));
                mx = fmaxf(mx, __shfl_xor_sync(0xffffffffu, mx, 2));
                float mnew = fmaxf(m_i[r], mx);
                corrv[r] = exp2f((m_i[r] - mnew) * C2);
                nm[r] = -mnew * C2;
                m_i[r] = mnew;
            }

            float rs0 = 0.f, rs1 = 0.f;
            uint32_t pu[32];
            #pragma unroll
            for (int nt = 0; nt < 16; nt++) {
                float p0 = exp2f(fmaf(sfrag[nt][0], C2, nm[0]));
                float p1 = exp2f(fmaf(sfrag[nt][1], C2, nm[0]));
                float p2 = exp2f(fmaf(sfrag[nt][2], C2, nm[1]));
                float p3 = exp2f(fmaf(sfrag[nt][3], C2, nm[1]));
                rs0 += p0 + p1;
                rs1 += p2 + p3;
                __half2 pa = __floats2half2_rn(p0, p1);
                __half2 pb = __floats2half2_rn(p2, p3);
                pu[2*nt]   = *(uint32_t*)&pa;
                pu[2*nt+1] = *(uint32_t*)&pb;
            }
            rs0 += __shfl_xor_sync(0xffffffffu, rs0, 1);
            rs0 += __shfl_xor_sync(0xffffffffu, rs0, 2);
            rs1 += __shfl_xor_sync(0xffffffffu, rs1, 1);
            rs1 += __shfl_xor_sync(0xffffffffu, rs1, 2);
            l_i[0] = l_i[0] * corrv[0] + rs0;
            l_i[1] = l_i[1] * corrv[1] + rs1;
            #pragma unroll
            for (int nt = 0; nt < 8; nt++) {
                ofrag[nt][0] *= corrv[0]; ofrag[nt][1] *= corrv[0];
                ofrag[nt][2] *= corrv[1]; ofrag[nt][3] *= corrv[1];
            }

            // ---- O += P V ----
            for (int ks = 0; ks <= npmax; ks++) {
                const uint32_t* pH = &pu[4 * ks];
                #pragma unroll
                for (int np = 0; np < 4; np++) {
                    uint32_t va = ((ks * 16 + vb_row) * AT_ST + np * 16 + vb_col) * 2;
                    uint32_t vh[4];
                    LDSM_X4_T(vh[0], vh[1], vh[2], vh[3], Vh_b + va);
                    mma_f16(ofrag[2*np],   pH, &vh[0]);
                    mma_f16(ofrag[2*np+1], pH, &vh[2]);
                }
            }
        }
    }

    // ---- epilogue: normalized output, fp16 ----
    const float inv0 = 1.f / l_i[0], inv1 = 1.f / l_i[1];
    const int row0 = q0 + wq + (lane >> 2);
    const size_t obase = (size_t)(b * TLEN + row0) * CD + h * DH;
    #pragma unroll
    for (int nt = 0; nt < 8; nt++) {
        int col = nt * 8 + (lane & 3) * 2;
        __half2 o0 = __floats2half2_rn(ofrag[nt][0] * inv0, ofrag[nt][1] * inv0);
        __half2 o1 = __floats2half2_rn(ofrag[nt][2] * inv1, ofrag[nt][3] * inv1);
        *(uint32_t*)(yh + obase + col) = *(uint32_t*)&o0;
        *(uint32_t*)(yh + obase + (size_t)8 * CD + col) = *(uint32_t*)&o1;
    }
}

// ---------------------------------------------------------------------------
extern "C" void kernel_launch(void* const* d_in, const int* in_sizes, int n_in,
                              void* d_out, int out_size)
{
    const float* x      = (const float*)d_in[0];
    const float* W_attn = (const float*)d_in[1];
    const float* b_attn = (const float*)d_in[2];
    const float* W_proj = (const float*)d_in[3];
    const float* b_proj = (const float*)d_in[4];
    float* out = (float*)d_out;

    __half *xh, *wah, *wph, *qkvh, *yh;
    cudaGetSymbolAddress((void**)&xh,   g_xh);
    cudaGetSymbolAddress((void**)&wah,  g_wah);
    cudaGetSymbolAddress((void**)&wph,  g_wph);
    cudaGetSymbolAddress((void**)&qkvh, g_qkvh);
    cudaGetSymbolAddress((void**)&yh,   g_yh);

    cudaFuncSetAttribute(gemm_f16<true>,
        cudaFuncAttributeMaxDynamicSharedMemorySize, GEMM_SMEM_B);
    cudaFuncSetAttribute(gemm_f16<false>,
        cudaFuncAttributeMaxDynamicSharedMemorySize, GEMM_SMEM_B);
    cudaFuncSetAttribute(attn_mma,
        cudaFuncAttributeMaxDynamicSharedMemorySize, ATTN_SMEM_B);

    // 0) merged pre-pass: fp32 -> fp16 (x, W_attn, W_proj)
    conv_all<<<(ALLN4 + 255) / 256, 256>>>(x, W_attn, W_proj, xh, wah, wph);

    // 1) qkv = x @ W_attn + b_attn  -> fp16 [4096, 3072]
    dim3 g1(C3 / 128, BT / 128);
    gemm_f16<true><<<g1, 256, GEMM_SMEM_B>>>(
        xh, wah, b_attn, nullptr, qkvh, C3, CD);

    // 2) causal flash attention -> fp16 y [4096, 1024]
    dim3 g2(TLEN / 128, NH, 2);
    attn_mma<<<g2, 256, ATTN_SMEM_B>>>(qkvh, yh);

    // 3) out = y @ W_proj + b_proj  -> fp32 [4096, 1024]
    dim3 g3(CD / 128, BT / 128);
    gemm_f16<false><<<g3, 256, GEMM_SMEM_B>>>(
        yh, wph, b_proj, out, nullptr, CD, CD);
}

// round 16
// speedup vs baseline: 1.5656x; 1.5656x over previous
#include <cuda_runtime.h>
#include <cuda_fp16.h>
#include <cstdint>

// Problem constants
#define BT    4096      // B*T
#define CD    1024      // C
#define C3    3072      // 3C
#define TLEN  2048
#define NH    16
#define DH    64

// ---------------------------------------------------------------------------
// Device-global scratch (allocation-free rule) — all plain fp16
// ---------------------------------------------------------------------------
__device__ __half g_xh[BT * CD];       // x fp16
__device__ __half g_wah[CD * C3];      // W_attn fp16
__device__ __half g_wph[CD * CD];      // W_proj fp16
__device__ __half g_qkvh[BT * C3];     // qkv fp16
__device__ __half g_yh[BT * CD];       // attn out fp16

// ---------------------------------------------------------------------------
// helpers
// ---------------------------------------------------------------------------
__device__ __forceinline__ uint32_t smem_u32(const void* p) {
    uint32_t a;
    asm("{ .reg .u64 t; cvta.to.shared.u64 t, %1; cvt.u32.u64 %0, t; }"
        : "=r"(a) : "l"(p));
    return a;
}

#define LDSM_X4(r0, r1, r2, r3, addr)                                          \
    asm volatile("ldmatrix.sync.aligned.m8n8.x4.shared.b16 {%0,%1,%2,%3}, [%4];" \
                 : "=r"(r0), "=r"(r1), "=r"(r2), "=r"(r3) : "r"(addr))

#define LDSM_X4_T(r0, r1, r2, r3, addr)                                        \
    asm volatile("ldmatrix.sync.aligned.m8n8.x4.trans.shared.b16 {%0,%1,%2,%3}, [%4];" \
                 : "=r"(r0), "=r"(r1), "=r"(r2), "=r"(r3) : "r"(addr))

__device__ __forceinline__ void mma_f16(float* d, const uint32_t* a,
                                        const uint32_t* b) {
    asm volatile(
        "mma.sync.aligned.m16n8k16.row.col.f32.f16.f16.f32 "
        "{%0,%1,%2,%3}, {%4,%5,%6,%7}, {%8,%9}, {%0,%1,%2,%3};"
        : "+f"(d[0]), "+f"(d[1]), "+f"(d[2]), "+f"(d[3])
        : "r"(a[0]), "r"(a[1]), "r"(a[2]), "r"(a[3]), "r"(b[0]), "r"(b[1]));
}

__device__ __forceinline__ void cp16(uint32_t s, const void* g) {
    asm volatile("cp.async.cg.shared.global [%0], [%1], 16;" :: "r"(s), "l"(g));
}
#define CP_COMMIT() asm volatile("cp.async.commit_group;" ::: "memory")
#define CP_WAIT0()  asm volatile("cp.async.wait_group 0;" ::: "memory")
#define CP_WAIT1()  asm volatile("cp.async.wait_group 1;" ::: "memory")

// ---------------------------------------------------------------------------
// Merged pre-pass: convert x, W_attn, W_proj fp32 -> fp16 in one launch
// ---------------------------------------------------------------------------
#define XN4  (BT * CD / 4)        // 1048576
#define WAN4 (CD * C3 / 4)        // 786432
#define WPN4 (CD * CD / 4)        // 262144
#define ALLN4 (XN4 + WAN4 + WPN4) // 2097152

__global__ void conv_all(const float* __restrict__ x,
                         const float* __restrict__ wa,
                         const float* __restrict__ wp,
                         __half* __restrict__ xh,
                         __half* __restrict__ wah,
                         __half* __restrict__ wph)
{
    int i = blockIdx.x * blockDim.x + threadIdx.x;
    if (i >= ALLN4) return;
    const float* s; __half* d; int off;
    if (i < XN4)             { s = x;  d = xh;  off = i; }
    else if (i < XN4 + WAN4) { s = wa; d = wah; off = i - XN4; }
    else                     { s = wp; d = wph; off = i - XN4 - WAN4; }
    float4 v = ((const float4*)s)[off];
    __half2 a = __floats2half2_rn(v.x, v.y);
    __half2 b = __floats2half2_rn(v.z, v.w);
    *(uint2*)(d + (size_t)off * 4) = make_uint2(*(uint32_t*)&a, *(uint32_t*)&b);
}

// ---------------------------------------------------------------------------
// Plain fp16 HMMA GEMM: BK=32, 3-stage cp.async pipeline, ONE sync per stage.
// C[M,N] = A[M,K] @ B[K,N] + bias    (fp32 accumulate)
// CTA tile 128x128, 8 warps (4m x 2n), warp tile 32x64, 2 CTAs/SM.
// Loop: wait_group 1 -> sync -> issue load(s+2) -> compute(s).
// Safety: load(s+2) overwrites buffer (s-1)%3; top sync proves compute(s-1)
// finished in all warps. Load(s) has 2 compute-stages of latency cover.
// ---------------------------------------------------------------------------
#define GA_ST 40
#define GB_ST 136
#define SA_SZ (128 * GA_ST)
#define SB_SZ (32 * GB_ST)
#define STG_H (SA_SZ + SB_SZ)
#define GEMM_SMEM_B (3 * STG_H * 2)   // 56832 bytes

template <bool FP16_OUT>
__global__ __launch_bounds__(256, 2) void gemm_f16(
    const __half* __restrict__ Ah_,
    const __half* __restrict__ Bh_,
    const float* __restrict__ bias, float* __restrict__ C,
    __half* __restrict__ Ch,
    int N, int K)
{
    extern __shared__ __half smg[];
    const uint32_t sb = smem_u32(smg);

    const int tid  = threadIdx.x;
    const int wid  = tid >> 5;
    const int lane = tid & 31;
    const int bm   = blockIdx.y * 128;
    const int bn   = blockIdx.x * 128;
    const int wm   = (wid & 3) * 32;
    const int wn   = (wid >> 2) * 64;

    const int nstages = K >> 5;

    auto load_stage = [&](int s) {
        const int k0 = s << 5;
        const uint32_t base = (uint32_t)(s % 3) * STG_H;
        #pragma unroll
        for (int i = 0; i < 2; i++) {
            int idx = tid + i * 256;
            int r = idx >> 2, c = idx & 3;
            size_t g = (size_t)(bm + r) * K + k0 + c * 8;
            cp16(sb + (base + r * GA_ST + c * 8) * 2, Ah_ + g);
        }
        #pragma unroll
        for (int i = 0; i < 2; i++) {
            int idx = tid + i * 256;
            int r = idx >> 4, c = idx & 15;
            size_t g = (size_t)(k0 + r) * N + bn + c * 8;
            cp16(sb + (base + SA_SZ + r * GB_ST + c * 8) * 2, Bh_ + g);
        }
        CP_COMMIT();
    };

    float acc[2][8][4];
    #pragma unroll
    for (int i = 0; i < 2; i++)
        #pragma unroll
        for (int j = 0; j < 8; j++)
            #pragma unroll
            for (int r = 0; r < 4; r++) acc[i][j][r] = 0.f;

    const int a_row = wm + (lane & 15);
    const int a_col = (lane >> 4) * 8;
    const int b_row = (lane & 7) + ((lane >> 3) & 1) * 8;
    const int b_col = wn + (lane >> 4) * 8;

    load_stage(0);
    load_stage(1);

    for (int s = 0; s < nstages; s++) {
        // wait for oldest in-flight load (stage s), allow stage s+1 in flight
        if (s + 1 < nstages) CP_WAIT1(); else CP_WAIT0();
        __syncthreads();   // publishes stage-s data; proves compute(s-1) done
        if (s + 2 < nstages) load_stage(s + 2);

        const uint32_t base = (uint32_t)(s % 3) * STG_H;
        const uint32_t aH_b = sb + base * 2;
        const uint32_t bH_b = aH_b + SA_SZ * 2;

        #pragma unroll
        for (int kk = 0; kk < 32; kk += 16) {
            uint32_t aH[2][4];
            #pragma unroll
            for (int mf = 0; mf < 2; mf++) {
                uint32_t off = ((a_row + mf * 16) * GA_ST + a_col + kk) * 2;
                LDSM_X4(aH[mf][0], aH[mf][1], aH[mf][2], aH[mf][3], aH_b + off);
            }
            #pragma unroll
            for (int nf2 = 0; nf2 < 4; nf2++) {
                uint32_t off = ((b_row + kk) * GB_ST + b_col + nf2 * 16) * 2;
                uint32_t bH[4];
                LDSM_X4_T(bH[0], bH[1], bH[2], bH[3], bH_b + off);
                #pragma unroll
                for (int mf = 0; mf < 2; mf++) {
                    #pragma unroll
                    for (int h = 0; h < 2; h++) {
                        mma_f16(acc[mf][nf2 * 2 + h], aH[mf], &bH[h * 2]);
                    }
                }
            }
        }
    }

    const int rbase = bm + wm + (lane >> 2);
    const int cbase = bn + wn + (lane & 3) * 2;
    #pragma unroll
    for (int mf = 0; mf < 2; mf++) {
        #pragma unroll
        for (int nf = 0; nf < 8; nf++) {
            int col = cbase + nf * 8;
            float b0 = bias[col], b1 = bias[col + 1];
            int r0 = rbase + mf * 16;
            float v00 = acc[mf][nf][0] + b0, v01 = acc[mf][nf][1] + b1;
            float v10 = acc[mf][nf][2] + b0, v11 = acc[mf][nf][3] + b1;
            if (FP16_OUT) {
                __half2 o0 = __floats2half2_rn(v00, v01);
                __half2 o1 = __floats2half2_rn(v10, v11);
                *(uint32_t*)(Ch + (size_t)r0 * N + col)       = *(uint32_t*)&o0;
                *(uint32_t*)(Ch + (size_t)(r0 + 8) * N + col) = *(uint32_t*)&o1;
            } else {
                *(float2*)(C + (size_t)r0 * N + col)       = make_float2(v00, v01);
                *(float2*)(C + (size_t)(r0 + 8) * N + col) = make_float2(v10, v11);
            }
        }
    }
}

// ---------------------------------------------------------------------------
// Causal flash attention (R13-exact: known-good 232.2 config).
// Q tile 128 rows (8 warps x 16 q-rows, 256 thr); 128-key K/V tiles,
// cp.async double-buffered, two syncs per tile. smem 92160 B -> 2 CTAs/SM.
// ---------------------------------------------------------------------------
#define AT_ST 72
#define QT_SZ (128 * AT_ST)                      // 9216 halves
#define KT_SZ (128 * AT_ST)                      // 9216 halves (K or V tile)
#define KV_STG (2 * KT_SZ)                       // 18432 halves per stage
#define ATTN_SMEM_B ((QT_SZ + 2 * KV_STG) * 2)   // 92160 bytes
#define C2 0.18033688011112042f                  // 0.125 * log2(e)

__global__ __launch_bounds__(256, 2) void attn_mma(
    const __half* __restrict__ qh_g, __half* __restrict__ yh)
{
    extern __shared__ __half sma[];
    const uint32_t sb = smem_u32(sma);
    const uint32_t Qh_b = sb;

    const int qt   = (int)gridDim.x - 1 - (int)blockIdx.x;  // heavy first
    const int h    = blockIdx.y;
    const int b    = blockIdx.z;
    const int tid  = threadIdx.x;
    const int wid  = tid >> 5;          // 0..7
    const int lane = tid & 31;
    const int q0   = qt * 128;
    const int wq   = wid * 16;

    // ---- Q tile (128 rows), part of first cp.async group ----
    {
        const size_t qbase = (size_t)(b * TLEN + q0) * C3 + h * DH;
        #pragma unroll
        for (int i = 0; i < 4; i++) {
            int idx = tid + i * 256;
            int r = idx >> 3, c = idx & 7;
            cp16(Qh_b + (r * AT_ST + c * 8) * 2, qh_g + qbase + (size_t)r * C3 + c * 8);
        }
    }

    auto load_kv = [&](int kt) {
        const uint32_t kvb = sb + (QT_SZ + (uint32_t)(kt & 1) * KV_STG) * 2;
        const size_t kbase = (size_t)(b * TLEN + kt * 128) * C3 + CD + h * DH;
        const size_t vbase = kbase + CD;
        #pragma unroll
        for (int i = 0; i < 4; i++) {
            int idx = tid + i * 256;
            int r = idx >> 3, c = idx & 7;
            uint32_t so = (r * AT_ST + c * 8) * 2;
            cp16(kvb + so,             qh_g + kbase + (size_t)r * C3 + c * 8);
            cp16(kvb + so + KT_SZ * 2, qh_g + vbase + (size_t)r * C3 + c * 8);
        }
        CP_COMMIT();
    };

    load_kv(0);

    float m_i[2] = {-1e30f, -1e30f}, l_i[2] = {0.f, 0.f};
    float ofrag[8][4];
    #pragma unroll
    for (int nt = 0; nt < 8; nt++)
        #pragma unroll
        for (int r = 0; r < 4; r++) ofrag[nt][r] = 0.f;

    const int qa_row = wq + (lane & 15);
    const int qa_col = (lane >> 4) * 8;
    const int kb_row = ((lane >> 4) << 3) + (lane & 7);
    const int kb_col = ((lane >> 3) & 1) * 8;
    const int vb_row = (lane & 7) + ((lane >> 3) & 1) * 8;
    const int vb_col = (lane >> 4) * 8;

    const int nkt = qt + 1;

    for (int kt = 0; kt < nkt; kt++) {
        if (kt + 1 < nkt) load_kv(kt + 1);
        if (kt + 1 < nkt) CP_WAIT1(); else CP_WAIT0();
        __syncthreads();

        const uint32_t kvb  = sb + (QT_SZ + (uint32_t)(kt & 1) * KV_STG) * 2;
        const uint32_t Kh_b = kvb;
        const uint32_t Vh_b = kvb + KT_SZ * 2;

        // rel >= 0: this warp has at least one unmasked key in this 128-key tile
        const int rel = q0 + wq + 15 - 128 * kt;
        if (rel >= 0) {
            const int npmax = min(7, rel >> 4);   // 16-key subtiles with work

            // ---- S = Q K^T (raw, unscaled) ----
            float sfrag[16][4];
            #pragma unroll
            for (int nt = 0; nt < 16; nt++)
                #pragma unroll
                for (int r = 0; r < 4; r++) sfrag[nt][r] = 0.f;

            #pragma unroll
            for (int ks = 0; ks < 4; ks++) {
                uint32_t qh[4];
                uint32_t qa = (qa_row * AT_ST + ks * 16 + qa_col) * 2;
                LDSM_X4(qh[0], qh[1], qh[2], qh[3], Qh_b + qa);
                for (int np = 0; np <= npmax; np++) {
                    uint32_t ka = ((np * 16 + kb_row) * AT_ST + ks * 16 + kb_col) * 2;
                    uint32_t kh[4];
                    LDSM_X4(kh[0], kh[1], kh[2], kh[3], Kh_b + ka);
                    mma_f16(sfrag[2*np],   qh, &kh[0]);
                    mma_f16(sfrag[2*np+1], qh, &kh[2]);
                }
            }

            // ---- causal mask (raw domain; covers uncomputed subtiles too) ----
            if (rel < 142) {
                #pragma unroll
                for (int nt = 0; nt < 16; nt++) {
                    #pragma unroll
                    for (int r = 0; r < 4; r++) {
                        int gcol = 128 * kt + nt * 8 + (lane & 3) * 2 + (r & 1);
                        int grow = q0 + wq + (lane >> 2) + (r >> 1) * 8;
                        if (gcol > grow) sfrag[nt][r] = -1e30f;
                    }
                }
            }

            // ---- online softmax: raw max, scale folded into exp2 ----
            float corrv[2], nm[2];
            #pragma unroll
            for (int r = 0; r < 2; r++) {
                float mx = -1e30f;
                #pragma unroll
                for (int nt = 0; nt < 16; nt++)
                    mx = fmaxf(mx, fmaxf(sfrag[nt][2*r], sfrag[nt][2*r+1]));
                mx = fmaxf(mx, __shfl_xor_sync(0xffffffffu, mx, 1));
                mx = fmaxf(mx, __shfl_xor_sync(0xffffffffu, mx, 2));
                float mnew = fmaxf(m_i[r], mx);
                corrv[r] = exp2f((m_i[r] - mnew) * C2);
                nm[r] = -mnew * C2;
                m_i[r] = mnew;
            }

            float rs0 = 0.f, rs1 = 0.f;
            uint32_t pu[32];
            #pragma unroll
            for (int nt = 0; nt < 16; nt++) {
                float p0 = exp2f(fmaf(sfrag[nt][0], C2, nm[0]));
                float p1 = exp2f(fmaf(sfrag[nt][1], C2, nm[0]));
                float p2 = exp2f(fmaf(sfrag[nt][2], C2, nm[1]));
                float p3 = exp2f(fmaf(sfrag[nt][3], C2, nm[1]));
                rs0 += p0 + p1;
                rs1 += p2 + p3;
                __half2 pa = __floats2half2_rn(p0, p1);
                __half2 pb = __floats2half2_rn(p2, p3);
                pu[2*nt]   = *(uint32_t*)&pa;
                pu[2*nt+1] = *(uint32_t*)&pb;
            }
            rs0 += __shfl_xor_sync(0xffffffffu, rs0, 1);
            rs0 += __shfl_xor_sync(0xffffffffu, rs0, 2);
            rs1 += __shfl_xor_sync(0xffffffffu, rs1, 1);
            rs1 += __shfl_xor_sync(0xffffffffu, rs1, 2);
            l_i[0] = l_i[0] * corrv[0] + rs0;
            l_i[1] = l_i[1] * corrv[1] + rs1;
            #pragma unroll
            for (int nt = 0; nt < 8; nt++) {
                ofrag[nt][0] *= corrv[0]; ofrag[nt][1] *= corrv[0];
                ofrag[nt][2] *= corrv[1]; ofrag[nt][3] *= corrv[1];
            }

            // ---- O += P V ----
            for (int ks = 0; ks <= npmax; ks++) {
                const uint32_t* pH = &pu[4 * ks];
                #pragma unroll
                for (int np = 0; np < 4; np++) {
                    uint32_t va = ((ks * 16 + vb_row) * AT_ST + np * 16 + vb_col) * 2;
                    uint32_t vh[4];
                    LDSM_X4_T(vh[0], vh[1], vh[2], vh[3], Vh_b + va);
                    mma_f16(ofrag[2*np],   pH, &vh[0]);
                    mma_f16(ofrag[2*np+1], pH, &vh[2]);
                }
            }
        }
        __syncthreads();
    }

    // ---- epilogue: normalized output, fp16 ----
    const float inv0 = 1.f / l_i[0], inv1 = 1.f / l_i[1];
    const int row0 = q0 + wq + (lane >> 2);
    const size_t obase = (size_t)(b * TLEN + row0) * CD + h * DH;
    #pragma unroll
    for (int nt = 0; nt < 8; nt++) {
        int col = nt * 8 + (lane & 3) * 2;
        __half2 o0 = __floats2half2_rn(ofrag[nt][0] * inv0, ofrag[nt][1] * inv0);
        __half2 o1 = __floats2half2_rn(ofrag[nt][2] * inv1, ofrag[nt][3] * inv1);
        *(uint32_t*)(yh + obase + col) = *(uint32_t*)&o0;
        *(uint32_t*)(yh + obase + (size_t)8 * CD + col) = *(uint32_t*)&o1;
    }
}

// ---------------------------------------------------------------------------
extern "C" void kernel_launch(void* const* d_in, const int* in_sizes, int n_in,
                              void* d_out, int out_size)
{
    const float* x      = (const float*)d_in[0];
    const float* W_attn = (const float*)d_in[1];
    const float* b_attn = (const float*)d_in[2];
    const float* W_proj = (const float*)d_in[3];
    const float* b_proj = (const float*)d_in[4];
    float* out = (float*)d_out;

    __half *xh, *wah, *wph, *qkvh, *yh;
    cudaGetSymbolAddress((void**)&xh,   g_xh);
    cudaGetSymbolAddress((void**)&wah,  g_wah);
    cudaGetSymbolAddress((void**)&wph,  g_wph);
    cudaGetSymbolAddress((void**)&qkvh, g_qkvh);
    cudaGetSymbolAddress((void**)&yh,   g_yh);

    cudaFuncSetAttribute(gemm_f16<true>,
        cudaFuncAttributeMaxDynamicSharedMemorySize, GEMM_SMEM_B);
    cudaFuncSetAttribute(gemm_f16<false>,
        cudaFuncAttributeMaxDynamicSharedMemorySize, GEMM_SMEM_B);
    cudaFuncSetAttribute(attn_mma,
        cudaFuncAttributeMaxDynamicSharedMemorySize, ATTN_SMEM_B);

    // 0) merged pre-pass: fp32 -> fp16 (x, W_attn, W_proj)
    conv_all<<<(ALLN4 + 255) / 256, 256>>>(x, W_attn, W_proj, xh, wah, wph);

    // 1) qkv = x @ W_attn + b_attn  -> fp16 [4096, 3072]
    dim3 g1(C3 / 128, BT / 128);
    gemm_f16<true><<<g1, 256, GEMM_SMEM_B>>>(
        xh, wah, b_attn, nullptr, qkvh, C3, CD);

    // 2) causal flash attention -> fp16 y [4096, 1024]
    dim3 g2(TLEN / 128, NH, 2);
    attn_mma<<<g2, 256, ATTN_SMEM_B>>>(qkvh, yh);

    // 3) out = y @ W_proj + b_proj  -> fp32 [4096, 1024]
    dim3 g3(CD / 128, BT / 128);
    gemm_f16<false><<<g3, 256, GEMM_SMEM_B>>>(
        yh, wph, b_proj, out, nullptr, CD, CD);
}

// round 17
// speedup vs baseline: 1.5795x; 1.0089x over previous
#include <cuda_runtime.h>
#include <cuda_fp16.h>
#include <cstdint>

// Problem constants
#define BT    4096      // B*T
#define CD    1024      // C
#define C3    3072      // 3C
#define TLEN  2048
#define NH    16
#define DH    64

// ---------------------------------------------------------------------------
// Device-global scratch (allocation-free rule) — all plain fp16
// ---------------------------------------------------------------------------
__device__ __half g_xh[BT * CD];       // x fp16
__device__ __half g_wah[CD * C3];      // W_attn fp16
__device__ __half g_wph[CD * CD];      // W_proj fp16
__device__ __half g_qkvh[BT * C3];     // qkv fp16
__device__ __half g_yh[BT * CD];       // attn out fp16

// ---------------------------------------------------------------------------
// helpers
// ---------------------------------------------------------------------------
__device__ __forceinline__ uint32_t smem_u32(const void* p) {
    uint32_t a;
    asm("{ .reg .u64 t; cvta.to.shared.u64 t, %1; cvt.u32.u64 %0, t; }"
        : "=r"(a) : "l"(p));
    return a;
}

#define LDSM_X4(r0, r1, r2, r3, addr)                                          \
    asm volatile("ldmatrix.sync.aligned.m8n8.x4.shared.b16 {%0,%1,%2,%3}, [%4];" \
                 : "=r"(r0), "=r"(r1), "=r"(r2), "=r"(r3) : "r"(addr))

#define LDSM_X4_T(r0, r1, r2, r3, addr)                                        \
    asm volatile("ldmatrix.sync.aligned.m8n8.x4.trans.shared.b16 {%0,%1,%2,%3}, [%4];" \
                 : "=r"(r0), "=r"(r1), "=r"(r2), "=r"(r3) : "r"(addr))

__device__ __forceinline__ void mma_f16(float* d, const uint32_t* a,
                                        const uint32_t* b) {
    asm volatile(
        "mma.sync.aligned.m16n8k16.row.col.f32.f16.f16.f32 "
        "{%0,%1,%2,%3}, {%4,%5,%6,%7}, {%8,%9}, {%0,%1,%2,%3};"
        : "+f"(d[0]), "+f"(d[1]), "+f"(d[2]), "+f"(d[3])
        : "r"(a[0]), "r"(a[1]), "r"(a[2]), "r"(a[3]), "r"(b[0]), "r"(b[1]));
}

__device__ __forceinline__ void cp16(uint32_t s, const void* g) {
    asm volatile("cp.async.cg.shared.global [%0], [%1], 16;" :: "r"(s), "l"(g));
}
#define CP_COMMIT() asm volatile("cp.async.commit_group;" ::: "memory")
#define CP_WAIT0()  asm volatile("cp.async.wait_group 0;" ::: "memory")
#define CP_WAIT1()  asm volatile("cp.async.wait_group 1;" ::: "memory")

// ---------------------------------------------------------------------------
// Merged pre-pass: convert x, W_attn, W_proj fp32 -> fp16 in one launch
// ---------------------------------------------------------------------------
#define XN4  (BT * CD / 4)        // 1048576
#define WAN4 (CD * C3 / 4)        // 786432
#define WPN4 (CD * CD / 4)        // 262144
#define ALLN4 (XN4 + WAN4 + WPN4) // 2097152

__global__ void conv_all(const float* __restrict__ x,
                         const float* __restrict__ wa,
                         const float* __restrict__ wp,
                         __half* __restrict__ xh,
                         __half* __restrict__ wah,
                         __half* __restrict__ wph)
{
    int i = blockIdx.x * blockDim.x + threadIdx.x;
    if (i >= ALLN4) return;
    const float* s; __half* d; int off;
    if (i < XN4)             { s = x;  d = xh;  off = i; }
    else if (i < XN4 + WAN4) { s = wa; d = wah; off = i - XN4; }
    else                     { s = wp; d = wph; off = i - XN4 - WAN4; }
    float4 v = ((const float4*)s)[off];
    __half2 a = __floats2half2_rn(v.x, v.y);
    __half2 b = __floats2half2_rn(v.z, v.w);
    *(uint2*)(d + (size_t)off * 4) = make_uint2(*(uint32_t*)&a, *(uint32_t*)&b);
}

// ---------------------------------------------------------------------------
// Plain fp16 HMMA GEMM: BK=32, 3-stage cp.async pipeline, ONE sync per stage.
// (R15-exact, known-good 221.1 config)
// ---------------------------------------------------------------------------
#define GA_ST 40
#define GB_ST 136
#define SA_SZ (128 * GA_ST)
#define SB_SZ (32 * GB_ST)
#define STG_H (SA_SZ + SB_SZ)
#define GEMM_SMEM_B (3 * STG_H * 2)   // 56832 bytes

template <bool FP16_OUT>
__global__ __launch_bounds__(256, 2) void gemm_f16(
    const __half* __restrict__ Ah_,
    const __half* __restrict__ Bh_,
    const float* __restrict__ bias, float* __restrict__ C,
    __half* __restrict__ Ch,
    int N, int K)
{
    extern __shared__ __half smg[];
    const uint32_t sb = smem_u32(smg);

    const int tid  = threadIdx.x;
    const int wid  = tid >> 5;
    const int lane = tid & 31;
    const int bm   = blockIdx.y * 128;
    const int bn   = blockIdx.x * 128;
    const int wm   = (wid & 3) * 32;
    const int wn   = (wid >> 2) * 64;

    const int nstages = K >> 5;

    auto load_stage = [&](int s) {
        const int k0 = s << 5;
        const uint32_t base = (uint32_t)(s % 3) * STG_H;
        #pragma unroll
        for (int i = 0; i < 2; i++) {
            int idx = tid + i * 256;
            int r = idx >> 2, c = idx & 3;
            size_t g = (size_t)(bm + r) * K + k0 + c * 8;
            cp16(sb + (base + r * GA_ST + c * 8) * 2, Ah_ + g);
        }
        #pragma unroll
        for (int i = 0; i < 2; i++) {
            int idx = tid + i * 256;
            int r = idx >> 4, c = idx & 15;
            size_t g = (size_t)(k0 + r) * N + bn + c * 8;
            cp16(sb + (base + SA_SZ + r * GB_ST + c * 8) * 2, Bh_ + g);
        }
        CP_COMMIT();
    };

    float acc[2][8][4];
    #pragma unroll
    for (int i = 0; i < 2; i++)
        #pragma unroll
        for (int j = 0; j < 8; j++)
            #pragma unroll
            for (int r = 0; r < 4; r++) acc[i][j][r] = 0.f;

    const int a_row = wm + (lane & 15);
    const int a_col = (lane >> 4) * 8;
    const int b_row = (lane & 7) + ((lane >> 3) & 1) * 8;
    const int b_col = wn + (lane >> 4) * 8;

    load_stage(0);
    load_stage(1);

    for (int s = 0; s < nstages; s++) {
        if (s + 1 < nstages) CP_WAIT1(); else CP_WAIT0();
        __syncthreads();   // publishes stage-s data; proves compute(s-1) done
        if (s + 2 < nstages) load_stage(s + 2);

        const uint32_t base = (uint32_t)(s % 3) * STG_H;
        const uint32_t aH_b = sb + base * 2;
        const uint32_t bH_b = aH_b + SA_SZ * 2;

        #pragma unroll
        for (int kk = 0; kk < 32; kk += 16) {
            uint32_t aH[2][4];
            #pragma unroll
            for (int mf = 0; mf < 2; mf++) {
                uint32_t off = ((a_row + mf * 16) * GA_ST + a_col + kk) * 2;
                LDSM_X4(aH[mf][0], aH[mf][1], aH[mf][2], aH[mf][3], aH_b + off);
            }
            #pragma unroll
            for (int nf2 = 0; nf2 < 4; nf2++) {
                uint32_t off = ((b_row + kk) * GB_ST + b_col + nf2 * 16) * 2;
                uint32_t bH[4];
                LDSM_X4_T(bH[0], bH[1], bH[2], bH[3], bH_b + off);
                #pragma unroll
                for (int mf = 0; mf < 2; mf++) {
                    #pragma unroll
                    for (int h = 0; h < 2; h++) {
                        mma_f16(acc[mf][nf2 * 2 + h], aH[mf], &bH[h * 2]);
                    }
                }
            }
        }
    }

    const int rbase = bm + wm + (lane >> 2);
    const int cbase = bn + wn + (lane & 3) * 2;
    #pragma unroll
    for (int mf = 0; mf < 2; mf++) {
        #pragma unroll
        for (int nf = 0; nf < 8; nf++) {
            int col = cbase + nf * 8;
            float b0 = bias[col], b1 = bias[col + 1];
            int r0 = rbase + mf * 16;
            float v00 = acc[mf][nf][0] + b0, v01 = acc[mf][nf][1] + b1;
            float v10 = acc[mf][nf][2] + b0, v11 = acc[mf][nf][3] + b1;
            if (FP16_OUT) {
                __half2 o0 = __floats2half2_rn(v00, v01);
                __half2 o1 = __floats2half2_rn(v10, v11);
                *(uint32_t*)(Ch + (size_t)r0 * N + col)       = *(uint32_t*)&o0;
                *(uint32_t*)(Ch + (size_t)(r0 + 8) * N + col) = *(uint32_t*)&o1;
            } else {
                *(float2*)(C + (size_t)r0 * N + col)       = make_float2(v00, v01);
                *(float2*)(C + (size_t)(r0 + 8) * N + col) = make_float2(v10, v11);
            }
        }
    }
}

// ---------------------------------------------------------------------------
// Causal flash attention, fp16 operands / fp32 acc.
// Q tile 128 rows (8 warps x 16 q-rows, 256 thr); 128-key K/V tiles.
// SINGLE barrier per tile: wait -> sync -> issue load(kt+1) -> compute(kt).
// Safety: load(kt+1) overwrites buffer (kt+1)&1, last read by compute(kt-1);
// the top sync of iteration kt proves compute(kt-1) finished in all warps.
// Grid (16 qtiles, 16 heads, 2 batch). smem 92160 B -> 2 CTAs/SM.
// ---------------------------------------------------------------------------
#define AT_ST 72
#define QT_SZ (128 * AT_ST)                      // 9216 halves
#define KT_SZ (128 * AT_ST)                      // 9216 halves (K or V tile)
#define KV_STG (2 * KT_SZ)                       // 18432 halves per stage
#define ATTN_SMEM_B ((QT_SZ + 2 * KV_STG) * 2)   // 92160 bytes
#define C2 0.18033688011112042f                  // 0.125 * log2(e)

__global__ __launch_bounds__(256, 2) void attn_mma(
    const __half* __restrict__ qh_g, __half* __restrict__ yh)
{
    extern __shared__ __half sma[];
    const uint32_t sb = smem_u32(sma);
    const uint32_t Qh_b = sb;

    const int qt   = (int)gridDim.x - 1 - (int)blockIdx.x;  // heavy first
    const int h    = blockIdx.y;
    const int b    = blockIdx.z;
    const int tid  = threadIdx.x;
    const int wid  = tid >> 5;          // 0..7
    const int lane = tid & 31;
    const int q0   = qt * 128;
    const int wq   = wid * 16;

    // ---- Q tile (128 rows), part of first cp.async group ----
    {
        const size_t qbase = (size_t)(b * TLEN + q0) * C3 + h * DH;
        #pragma unroll
        for (int i = 0; i < 4; i++) {
            int idx = tid + i * 256;
            int r = idx >> 3, c = idx & 7;
            cp16(Qh_b + (r * AT_ST + c * 8) * 2, qh_g + qbase + (size_t)r * C3 + c * 8);
        }
    }

    auto load_kv = [&](int kt) {
        const uint32_t kvb = sb + (QT_SZ + (uint32_t)(kt & 1) * KV_STG) * 2;
        const size_t kbase = (size_t)(b * TLEN + kt * 128) * C3 + CD + h * DH;
        const size_t vbase = kbase + CD;
        #pragma unroll
        for (int i = 0; i < 4; i++) {
            int idx = tid + i * 256;
            int r = idx >> 3, c = idx & 7;
            uint32_t so = (r * AT_ST + c * 8) * 2;
            cp16(kvb + so,             qh_g + kbase + (size_t)r * C3 + c * 8);
            cp16(kvb + so + KT_SZ * 2, qh_g + vbase + (size_t)r * C3 + c * 8);
        }
        CP_COMMIT();
    };

    load_kv(0);

    float m_i[2] = {-1e30f, -1e30f}, l_i[2] = {0.f, 0.f};
    float ofrag[8][4];
    #pragma unroll
    for (int nt = 0; nt < 8; nt++)
        #pragma unroll
        for (int r = 0; r < 4; r++) ofrag[nt][r] = 0.f;

    const int qa_row = wq + (lane & 15);
    const int qa_col = (lane >> 4) * 8;
    const int kb_row = ((lane >> 4) << 3) + (lane & 7);
    const int kb_col = ((lane >> 3) & 1) * 8;
    const int vb_row = (lane & 7) + ((lane >> 3) & 1) * 8;
    const int vb_col = (lane >> 4) * 8;

    const int nkt = qt + 1;

    for (int kt = 0; kt < nkt; kt++) {
        // one barrier per tile: publishes load(kt) AND proves compute(kt-1) done
        CP_WAIT0();
        __syncthreads();
        if (kt + 1 < nkt) load_kv(kt + 1);

        const uint32_t kvb  = sb + (QT_SZ + (uint32_t)(kt & 1) * KV_STG) * 2;
        const uint32_t Kh_b = kvb;
        const uint32_t Vh_b = kvb + KT_SZ * 2;

        // rel >= 0: this warp has at least one unmasked key in this 128-key tile
        const int rel = q0 + wq + 15 - 128 * kt;
        if (rel >= 0) {
            const int npmax = min(7, rel >> 4);   // 16-key subtiles with work

            // ---- S = Q K^T (raw, unscaled) ----
            float sfrag[16][4];
            #pragma unroll
            for (int nt = 0; nt < 16; nt++)
                #pragma unroll
                for (int r = 0; r < 4; r++) sfrag[nt][r] = 0.f;

            #pragma unroll
            for (int ks = 0; ks < 4; ks++) {
                uint32_t qh[4];
                uint32_t qa = (qa_row * AT_ST + ks * 16 + qa_col) * 2;
                LDSM_X4(qh[0], qh[1], qh[2], qh[3], Qh_b + qa);
                for (int np = 0; np <= npmax; np++) {
                    uint32_t ka = ((np * 16 + kb_row) * AT_ST + ks * 16 + kb_col) * 2;
                    uint32_t kh[4];
                    LDSM_X4(kh[0], kh[1], kh[2], kh[3], Kh_b + ka);
                    mma_f16(sfrag[2*np],   qh, &kh[0]);
                    mma_f16(sfrag[2*np+1], qh, &kh[2]);
                }
            }

            // ---- causal mask (raw domain; covers uncomputed subtiles too) ----
            if (rel < 142) {
                #pragma unroll
                for (int nt = 0; nt < 16; nt++) {
                    #pragma unroll
                    for (int r = 0; r < 4; r++) {
                        int gcol = 128 * kt + nt * 8 + (lane & 3) * 2 + (r & 1);
                        int grow = q0 + wq + (lane >> 2) + (r >> 1) * 8;
                        if (gcol > grow) sfrag[nt][r] = -1e30f;
                    }
                }
            }

            // ---- online softmax: raw max, scale folded into exp2 ----
            float corrv[2], nm[2];
            #pragma unroll
            for (int r = 0; r < 2; r++) {
                float mx = -1e30f;
                #pragma unroll
                for (int nt = 0; nt < 16; nt++)
                    mx = fmaxf(mx, fmaxf(sfrag[nt][2*r], sfrag[nt][2*r+1]));
                mx = fmaxf(mx, __shfl_xor_sync(0xffffffffu, mx, 1));
                mx = fmaxf(mx, __shfl_xor_sync(0xffffffffu, mx, 2));
                float mnew = fmaxf(m_i[r], mx);
                corrv[r] = exp2f((m_i[r] - mnew) * C2);
                nm[r] = -mnew * C2;
                m_i[r] = mnew;
            }

            float rs0 = 0.f, rs1 = 0.f;
            uint32_t pu[32];
            #pragma unroll
            for (int nt = 0; nt < 16; nt++) {
                float p0 = exp2f(fmaf(sfrag[nt][0], C2, nm[0]));
                float p1 = exp2f(fmaf(sfrag[nt][1], C2, nm[0]));
                float p2 = exp2f(fmaf(sfrag[nt][2], C2, nm[1]));
                float p3 = exp2f(fmaf(sfrag[nt][3], C2, nm[1]));
                rs0 += p0 + p1;
                rs1 += p2 + p3;
                __half2 pa = __floats2half2_rn(p0, p1);
                __half2 pb = __floats2half2_rn(p2, p3);
                pu[2*nt]   = *(uint32_t*)&pa;
                pu[2*nt+1] = *(uint32_t*)&pb;
            }
            rs0 += __shfl_xor_sync(0xffffffffu, rs0, 1);
            rs0 += __shfl_xor_sync(0xffffffffu, rs0, 2);
            rs1 += __shfl_xor_sync(0xffffffffu, rs1, 1);
            rs1 += __shfl_xor_sync(0xffffffffu, rs1, 2);
            l_i[0] = l_i[0] * corrv[0] + rs0;
            l_i[1] = l_i[1] * corrv[1] + rs1;
            #pragma unroll
            for (int nt = 0; nt < 8; nt++) {
                ofrag[nt][0] *= corrv[0]; ofrag[nt][1] *= corrv[0];
                ofrag[nt][2] *= corrv[1]; ofrag[nt][3] *= corrv[1];
            }

            // ---- O += P V ----
            for (int ks = 0; ks <= npmax; ks++) {
                const uint32_t* pH = &pu[4 * ks];
                #pragma unroll
                for (int np = 0; np < 4; np++) {
                    uint32_t va = ((ks * 16 + vb_row) * AT_ST + np * 16 + vb_col) * 2;
                    uint32_t vh[4];
                    LDSM_X4_T(vh[0], vh[1], vh[2], vh[3], Vh_b + va);
                    mma_f16(ofrag[2*np],   pH, &vh[0]);
                    mma_f16(ofrag[2*np+1], pH, &vh[2]);
                }
            }
        }
    }

    // ---- epilogue: normalized output, fp16 ----
    const float inv0 = 1.f / l_i[0], inv1 = 1.f / l_i[1];
    const int row0 = q0 + wq + (lane >> 2);
    const size_t obase = (size_t)(b * TLEN + row0) * CD + h * DH;
    #pragma unroll
    for (int nt = 0; nt < 8; nt++) {
        int col = nt * 8 + (lane & 3) * 2;
        __half2 o0 = __floats2half2_rn(ofrag[nt][0] * inv0, ofrag[nt][1] * inv0);
        __half2 o1 = __floats2half2_rn(ofrag[nt][2] * inv1, ofrag[nt][3] * inv1);
        *(uint32_t*)(yh + obase + col) = *(uint32_t*)&o0;
        *(uint32_t*)(yh + obase + (size_t)8 * CD + col) = *(uint32_t*)&o1;
    }
}

// ---------------------------------------------------------------------------
extern "C" void kernel_launch(void* const* d_in, const int* in_sizes, int n_in,
                              void* d_out, int out_size)
{
    const float* x      = (const float*)d_in[0];
    const float* W_attn = (const float*)d_in[1];
    const float* b_attn = (const float*)d_in[2];
    const float* W_proj = (const float*)d_in[3];
    const float* b_proj = (const float*)d_in[4];
    float* out = (float*)d_out;

    __half *xh, *wah, *wph, *qkvh, *yh;
    cudaGetSymbolAddress((void**)&xh,   g_xh);
    cudaGetSymbolAddress((void**)&wah,  g_wah);
    cudaGetSymbolAddress((void**)&wph,  g_wph);
    cudaGetSymbolAddress((void**)&qkvh, g_qkvh);
    cudaGetSymbolAddress((void**)&yh,   g_yh);

    cudaFuncSetAttribute(gemm_f16<true>,
        cudaFuncAttributeMaxDynamicSharedMemorySize, GEMM_SMEM_B);
    cudaFuncSetAttribute(gemm_f16<false>,
        cudaFuncAttributeMaxDynamicSharedMemorySize, GEMM_SMEM_B);
    cudaFuncSetAttribute(attn_mma,
        cudaFuncAttributeMaxDynamicSharedMemorySize, ATTN_SMEM_B);

    // 0) merged pre-pass: fp32 -> fp16 (x, W_attn, W_proj)
    conv_all<<<(ALLN4 + 255) / 256, 256>>>(x, W_attn, W_proj, xh, wah, wph);

    // 1) qkv = x @ W_attn + b_attn  -> fp16 [4096, 3072]
    dim3 g1(C3 / 128, BT / 128);
    gemm_f16<true><<<g1, 256, GEMM_SMEM_B>>>(
        xh, wah, b_attn, nullptr, qkvh, C3, CD);

    // 2) causal flash attention -> fp16 y [4096, 1024]
    dim3 g2(TLEN / 128, NH, 2);
    attn_mma<<<g2, 256, ATTN_SMEM_B>>>(qkvh, yh);

    // 3) out = y @ W_proj + b_proj  -> fp32 [4096, 1024]
    dim3 g3(CD / 128, BT / 128);
    gemm_f16<false><<<g3, 256, GEMM_SMEM_B>>>(
        yh, wph, b_proj, out, nullptr, CD, CD);
}